// round 2
// baseline (speedup 1.0000x reference)
#include <cuda_runtime.h>

#define HH 256
#define WW 256
#define BB 2
#define CC 64
#define EPSV 1e-5f
#define NPIX (HH*WW)
#define NGRP 16                      // B * groups = 2*8
#define NELEM_GRP (8*NPIX*2)         // 8 channels * H*W * 2 cosets

typedef unsigned long long ull;

// ---------------- scratch (device globals: allowed) ----------------
__device__ float g_t[2][BB][CC][HH][WW];   // conv1 output (pre-gn2)
__device__ float g_s[2][BB][CC][HH][WW];   // skip 1x1 output (pre-gn)
__device__ float g_sum_x[NGRP], g_ssq_x[NGRP];
__device__ float g_sum_t[NGRP], g_ssq_t[NGRP];
__device__ float g_sum_s[NGRP], g_ssq_s[NGRP];
__device__ float g_mean1[NGRP], g_inv1[NGRP];
__device__ float g_mean2[NGRP], g_inv2[NGRP];
__device__ float g_means[NGRP], g_invs[NGRP];

// ---------------- f32x2 helpers ----------------
__device__ __forceinline__ ull pk2(float lo, float hi) {
    ull r; asm("mov.b64 %0, {%1,%2};" : "=l"(r) : "f"(lo), "f"(hi)); return r;
}
__device__ __forceinline__ void ffma2(ull& d, ull a, ull b) {
    asm("fma.rn.f32x2 %0, %1, %2, %0;" : "+l"(d) : "l"(a), "l"(b));
}
__device__ __forceinline__ float2 upk(ull v) {
    float2 f; asm("mov.b64 {%0,%1}, %2;" : "=f"(f.x), "=f"(f.y) : "l"(v)); return f;
}

// ---------------- small kernels ----------------
__global__ void zero_stats_k() {
    int i = threadIdx.x;
    if (i < NGRP) {
        g_sum_x[i] = 0.f; g_ssq_x[i] = 0.f;
        g_sum_t[i] = 0.f; g_ssq_t[i] = 0.f;
        g_sum_s[i] = 0.f; g_ssq_s[i] = 0.f;
    }
}

__global__ void stats_x_k(const float* __restrict__ x0, const float* __restrict__ x1) {
    int slab = blockIdx.y;                     // cs*16 + b*8 + g
    int cs = slab >> 4, b = (slab >> 3) & 1, g = slab & 7;
    const float* src = (cs ? x1 : x0) + ((size_t)(b*CC + g*8)) * NPIX
                       + (size_t)blockIdx.x * 16384;
    const float4* p = (const float4*)src;
    float s = 0.f, ss = 0.f;
    for (int i = threadIdx.x; i < 4096; i += 256) {
        float4 v = p[i];
        s  += (v.x + v.y) + (v.z + v.w);
        ss += (v.x*v.x + v.y*v.y) + (v.z*v.z + v.w*v.w);
    }
    __shared__ float sh[256], sh2[256];
    sh[threadIdx.x] = s; sh2[threadIdx.x] = ss;
    __syncthreads();
    for (int o = 128; o > 0; o >>= 1) {
        if (threadIdx.x < o) { sh[threadIdx.x] += sh[threadIdx.x+o]; sh2[threadIdx.x] += sh2[threadIdx.x+o]; }
        __syncthreads();
    }
    if (threadIdx.x == 0) {
        atomicAdd(&g_sum_x[b*8+g], sh[0]);
        atomicAdd(&g_ssq_x[b*8+g], sh2[0]);
    }
}

__global__ void finalize1_k() {
    int i = threadIdx.x;
    if (i < NGRP) {
        float n = (float)NELEM_GRP;
        float m = g_sum_x[i] / n;
        float v = g_ssq_x[i] / n - m*m;
        g_mean1[i] = m; g_inv1[i] = rsqrtf(v + EPSV);
    }
}

__global__ void finalize2_k() {
    int i = threadIdx.x;
    float n = (float)NELEM_GRP;
    if (i < NGRP) {
        float m = g_sum_t[i] / n;
        float v = g_ssq_t[i] / n - m*m;
        g_mean2[i] = m; g_inv2[i] = rsqrtf(v + EPSV);
    } else if (i < 2*NGRP) {
        int j = i - NGRP;
        float m = g_sum_s[j] / n;
        float v = g_ssq_s[j] / n - m*m;
        g_means[j] = m; g_invs[j] = rsqrtf(v + EPSV);
    }
}

// ---------------- fused conv kernel (f32x2 packed math) ----------------
#define TH 8
#define TW 16
#define NT 512
// smem: sW = 64*64*6 ull (weights duplicated as (w,w) pairs, layout
// [(o*64+ic)*6 + t], t0..3 = corner taps, t4 = center, t5 = skip/0)
#define NW_ULL (CC*CC*6)
#define SMEM_BYTES (NW_ULL*8 + (64+64+2048+2880)*4)

template<int PASS>
__global__ __launch_bounds__(NT, 1)
void conv_qc_k(const float* __restrict__ in0, const float* __restrict__ in1,
               const float* __restrict__ Wc, const float* __restrict__ Wk,
               const float* __restrict__ Bi,
               const float* __restrict__ Ga, const float* __restrict__ Be,
               const float* __restrict__ Ws, const float* __restrict__ Bs,
               const float* __restrict__ Gs, const float* __restrict__ BeS,
               float* __restrict__ Out)
{
    extern __shared__ ull smu[];
    ull*   sW     = smu;                         // NW_ULL
    float* sScale = (float*)(smu + NW_ULL);      // 64
    float* sShift = sScale + CC;                 // 64
    float* sSame  = sShift + CC;                 // [16][8][16] raw
    float* sCross = sSame + 2048;                // [16][9][20] normalized+relu

    int tid  = threadIdx.x;
    int warp = tid >> 5, lane = tid & 31;
    int ocb  = warp * 4;
    int r    = lane >> 2, cb = (lane & 3) * 4;
    int z = blockIdx.z; int b = z & 1, cs = z >> 1;
    int y0 = blockIdx.y * TH, xb = blockIdx.x * TW;

    const float* same_base;
    const float* cross_base;
    if (PASS == 1) {
        same_base  = (cs ? in1 : in0) + (size_t)b * CC * NPIX;
        cross_base = (cs ? in0 : in1) + (size_t)b * CC * NPIX;
    } else {
        same_base  = &g_t[cs][b][0][0][0];
        cross_base = &g_t[cs ^ 1][b][0][0][0];
    }
    const float* meanA = (PASS == 1) ? g_mean1 : g_mean2;
    const float* invA  = (PASS == 1) ? g_inv1  : g_inv2;

    // weights -> smem as duplicated f32x2 pairs
    for (int idx = tid; idx < NW_ULL; idx += NT) {
        int t = idx % 6, oi = idx / 6;
        float w;
        if (t < 4)       w = Wk[oi*4 + t];
        else if (t == 4) w = Wc[oi];
        else             w = (PASS == 1) ? Ws[oi] : 0.f;
        sW[idx] = pk2(w, w);
    }
    if (tid < CC) {
        int grp = tid >> 3;
        float m = meanA[b*8+grp], iv = invA[b*8+grp];
        float sc = iv * Ga[tid];
        sScale[tid] = sc;
        sShift[tid] = Be[tid] - m * sc;
    }

    ull acc2[4][2], accs2[4][2];
    #pragma unroll
    for (int o = 0; o < 4; ++o) {
        float bv = Bi[ocb+o];
        float bs = (PASS == 1) ? Bs[ocb+o] : 0.f;
        acc2[o][0] = pk2(bv, bv); acc2[o][1] = pk2(bv, bv);
        accs2[o][0] = pk2(bs, bs); accs2[o][1] = pk2(bs, bs);
    }

    for (int icc = 0; icc < 4; ++icc) {
        __syncthreads();
        // same-coset tile (raw)
        {
            int ic = tid >> 5, q = tid & 31;
            int row = q >> 2, c4 = (q & 3) * 4;
            const float* src = same_base + (size_t)(icc*16+ic)*NPIX
                               + (size_t)(y0+row)*WW + xb + c4;
            *(float4*)&sSame[ic*128 + row*16 + c4] = *(const float4*)src;
        }
        // cross-coset tile with halo, normalized+relu
        for (int idx = tid; idx < 16*9*17; idx += NT) {
            int ic = idx / 153, rem = idx % 153;
            int row = rem / 17, col = rem % 17;
            int gy = y0 + cs - 1 + row;
            int gx = xb + cs - 1 + col;
            int gic = icc*16 + ic;
            float v = 0.f;
            if ((unsigned)gy < HH && (unsigned)gx < WW) {
                float raw = cross_base[(size_t)gic*NPIX + (size_t)gy*WW + gx];
                v = fmaxf(fmaf(raw, sScale[gic], sShift[gic]), 0.f);
            }
            sCross[ic*180 + row*20 + col] = v;
        }
        __syncthreads();

        #pragma unroll 4
        for (int ic = 0; ic < 16; ++ic) {
            int gic = icc*16 + ic;
            float sc = sScale[gic], sf = sShift[gic];
            float4 rv = *(float4*)&sSame[ic*128 + r*16 + cb];
            float h0 = fmaxf(fmaf(rv.x, sc, sf), 0.f);
            float h1 = fmaxf(fmaf(rv.y, sc, sf), 0.f);
            float h2 = fmaxf(fmaf(rv.z, sc, sf), 0.f);
            float h3 = fmaxf(fmaf(rv.w, sc, sf), 0.f);
            ull hh01 = pk2(h0, h1), hh23 = pk2(h2, h3);
            ull rw01, rw23;
            if (PASS == 1) { rw01 = pk2(rv.x, rv.y); rw23 = pk2(rv.z, rv.w); }

            const float* crp = &sCross[ic*180 + r*20 + cb];
            float4 c0a = *(const float4*)crp;        float c04 = crp[4];
            float4 c1a = *(const float4*)(crp + 20); float c14 = crp[24];
            ull c0A0 = pk2(c0a.x, c0a.y), c0A1 = pk2(c0a.z, c0a.w);
            ull c0B0 = pk2(c0a.y, c0a.z), c0B1 = pk2(c0a.w, c04);
            ull c1A0 = pk2(c1a.x, c1a.y), c1A1 = pk2(c1a.z, c1a.w);
            ull c1B0 = pk2(c1a.y, c1a.z), c1B1 = pk2(c1a.w, c14);

            #pragma unroll
            for (int o = 0; o < 4; ++o) {
                const ull* wb = sW + (size_t)((ocb + o)*64 + gic)*6;
                ulonglong2 wk01 = *(const ulonglong2*)(wb);
                ulonglong2 wk23 = *(const ulonglong2*)(wb + 2);
                ulonglong2 wcs  = *(const ulonglong2*)(wb + 4);
                ffma2(acc2[o][0], wk01.x, c0A0); ffma2(acc2[o][1], wk01.x, c0A1);
                ffma2(acc2[o][0], wk01.y, c0B0); ffma2(acc2[o][1], wk01.y, c0B1);
                ffma2(acc2[o][0], wk23.x, c1A0); ffma2(acc2[o][1], wk23.x, c1A1);
                ffma2(acc2[o][0], wk23.y, c1B0); ffma2(acc2[o][1], wk23.y, c1B1);
                ffma2(acc2[o][0], wcs.x,  hh01); ffma2(acc2[o][1], wcs.x,  hh23);
                if (PASS == 1) {
                    ffma2(accs2[o][0], wcs.y, rw01);
                    ffma2(accs2[o][1], wcs.y, rw23);
                }
            }
        }
    }

    size_t pixoff = (size_t)(y0 + r) * WW + xb + cb;
    if (PASS == 1) {
        float st = 0.f, sst = 0.f, sv = 0.f, ssv = 0.f;
        #pragma unroll
        for (int o = 0; o < 4; ++o) {
            int oc = ocb + o;
            float2 a01 = upk(acc2[o][0]),  a23 = upk(acc2[o][1]);
            float2 s01 = upk(accs2[o][0]), s23 = upk(accs2[o][1]);
            float* tp = &g_t[cs][b][oc][0][0] + pixoff;
            float* sp = &g_s[cs][b][oc][0][0] + pixoff;
            *(float4*)tp = make_float4(a01.x, a01.y, a23.x, a23.y);
            *(float4*)sp = make_float4(s01.x, s01.y, s23.x, s23.y);
            st += (a01.x + a01.y) + (a23.x + a23.y);
            sst += a01.x*a01.x + a01.y*a01.y + a23.x*a23.x + a23.y*a23.y;
            sv += (s01.x + s01.y) + (s23.x + s23.y);
            ssv += s01.x*s01.x + s01.y*s01.y + s23.x*s23.x + s23.y*s23.y;
        }
        #pragma unroll
        for (int off = 16; off; off >>= 1) {
            st  += __shfl_xor_sync(0xffffffffu, st,  off);
            sst += __shfl_xor_sync(0xffffffffu, sst, off);
            sv  += __shfl_xor_sync(0xffffffffu, sv,  off);
            ssv += __shfl_xor_sync(0xffffffffu, ssv, off);
        }
        if (lane == 0) {
            int gi = b*8 + (ocb >> 3);
            atomicAdd(&g_sum_t[gi], st); atomicAdd(&g_ssq_t[gi], sst);
            atomicAdd(&g_sum_s[gi], sv); atomicAdd(&g_ssq_s[gi], ssv);
        }
    } else {
        #pragma unroll
        for (int o = 0; o < 4; ++o) {
            int oc = ocb + o;
            int gi = b*8 + (oc >> 3);
            float iv  = g_invs[gi];
            float gsc = Gs[oc] * iv;
            float gsh = BeS[oc] - g_means[gi] * gsc;
            const float* sp = &g_s[cs][b][oc][0][0] + pixoff;
            float4 sv4 = *(const float4*)sp;
            float2 a01 = upk(acc2[o][0]), a23 = upk(acc2[o][1]);
            float4 ov;
            ov.x = a01.x + fmaf(sv4.x, gsc, gsh);
            ov.y = a01.y + fmaf(sv4.y, gsc, gsh);
            ov.z = a23.x + fmaf(sv4.z, gsc, gsh);
            ov.w = a23.y + fmaf(sv4.w, gsc, gsh);
            float* op = Out + (((size_t)cs*BB + b)*CC + oc)*NPIX + pixoff;
            *(float4*)op = ov;
        }
    }
}

// ---------------- launch ----------------
extern "C" void kernel_launch(void* const* d_in, const int* in_sizes, int n_in,
                              void* d_out, int out_size) {
    const float* x0      = (const float*)d_in[0];
    const float* x1      = (const float*)d_in[1];
    const float* g1      = (const float*)d_in[2];
    const float* b1      = (const float*)d_in[3];
    const float* w1c     = (const float*)d_in[4];
    const float* w1k     = (const float*)d_in[5];
    const float* bias1   = (const float*)d_in[6];
    const float* g2      = (const float*)d_in[7];
    const float* b2      = (const float*)d_in[8];
    const float* w2c     = (const float*)d_in[9];
    const float* w2k     = (const float*)d_in[10];
    const float* bias2   = (const float*)d_in[11];
    const float* wskip   = (const float*)d_in[12];
    const float* bskip   = (const float*)d_in[13];
    const float* gskip   = (const float*)d_in[14];
    const float* betask  = (const float*)d_in[15];

    cudaFuncSetAttribute(conv_qc_k<1>, cudaFuncAttributeMaxDynamicSharedMemorySize, SMEM_BYTES);
    cudaFuncSetAttribute(conv_qc_k<2>, cudaFuncAttributeMaxDynamicSharedMemorySize, SMEM_BYTES);

    zero_stats_k<<<1, 128>>>();
    stats_x_k<<<dim3(32, 32), 256>>>(x0, x1);
    finalize1_k<<<1, 32>>>();

    dim3 grid(WW/TW, HH/TH, 4);   // z = b + 2*coset
    conv_qc_k<1><<<grid, NT, SMEM_BYTES>>>(x0, x1, w1c, w1k, bias1, g1, b1,
                                           wskip, bskip, nullptr, nullptr, nullptr);
    finalize2_k<<<1, 64>>>();
    conv_qc_k<2><<<grid, NT, SMEM_BYTES>>>(nullptr, nullptr, w2c, w2k, bias2, g2, b2,
                                           nullptr, nullptr, gskip, betask, (float*)d_out);
    (void)in_sizes; (void)n_in; (void)out_size;
}

// round 5
// speedup vs baseline: 1.0703x; 1.0703x over previous
#include <cuda_runtime.h>

#define HH 256
#define WW 256
#define BB 2
#define CC 64
#define EPSV 1e-5f
#define NPIX (HH*WW)
#define NGRP 16                      // B * groups
#define NELEM_GRP (8*NPIX*2)

// ---------------- scratch ----------------
__device__ float g_t[2][BB][CC][HH][WW];   // conv1 output (pre-gn2)
__device__ float g_s[2][BB][CC][HH][WW];   // skip 1x1 output (pre-gn)
__device__ float g_sum_x[NGRP], g_ssq_x[NGRP];
__device__ float g_sum_t[NGRP], g_ssq_t[NGRP];
__device__ float g_sum_s[NGRP], g_ssq_s[NGRP];
__device__ float g_mean1[NGRP], g_inv1[NGRP];
__device__ float g_mean2[NGRP], g_inv2[NGRP];
__device__ float g_means[NGRP], g_invs[NGRP];

// ---------------- small kernels ----------------
__global__ void zero_stats_k() {
    int i = threadIdx.x;
    if (i < NGRP) {
        g_sum_x[i] = 0.f; g_ssq_x[i] = 0.f;
        g_sum_t[i] = 0.f; g_ssq_t[i] = 0.f;
        g_sum_s[i] = 0.f; g_ssq_s[i] = 0.f;
    }
}

__global__ void finalize1_k() {
    int i = threadIdx.x;
    if (i < NGRP) {
        float n = (float)NELEM_GRP;
        float m = g_sum_x[i] / n;
        float v = g_ssq_x[i] / n - m*m;
        g_mean1[i] = m; g_inv1[i] = rsqrtf(v + EPSV);
    }
}

__global__ void finalize2_k() {
    int i = threadIdx.x;
    float n = (float)NELEM_GRP;
    if (i < NGRP) {
        float m = g_sum_t[i] / n;
        float v = g_ssq_t[i] / n - m*m;
        g_mean2[i] = m; g_inv2[i] = rsqrtf(v + EPSV);
    } else if (i < 2*NGRP) {
        int j = i - NGRP;
        float m = g_sum_s[j] / n;
        float v = g_ssq_s[j] / n - m*m;
        g_means[j] = m; g_invs[j] = rsqrtf(v + EPSV);
    }
}

// ---------------- skip kernel: s = Ws*x + bs; also x-stats & s-stats ----------------
// grid (16, 32, 8): z = half*4 + cs*2 + b. 256 thr = 8 warps; warp -> 4 oc.
__global__ __launch_bounds__(256, 4)
void skip_k(const float* __restrict__ x0, const float* __restrict__ x1,
            const float* __restrict__ Ws, const float* __restrict__ Bs)
{
    __shared__ float sW[32*64];   // this half's 32 oc rows
    __shared__ float sX[2048];    // [16][8][16]

    int tid = threadIdx.x, warp = tid >> 5, lane = tid & 31;
    int r = lane >> 2, cb = (lane & 3) * 4;
    int z = blockIdx.z; int b = z & 1, cs = (z >> 1) & 1, half = z >> 2;
    int oc0 = half * 32 + warp * 4;
    int y0 = blockIdx.y * 8, xb = blockIdx.x * 16;

    const float* xbase = (cs ? x1 : x0) + (size_t)b * CC * NPIX;

    for (int idx = tid; idx < 2048; idx += 256)
        sW[idx] = Ws[(size_t)(half*32 + (idx >> 6)) * 64 + (idx & 63)];

    float acc[4][4];
    #pragma unroll
    for (int o = 0; o < 4; ++o) {
        float bv = Bs[oc0 + o];
        #pragma unroll
        for (int p = 0; p < 4; ++p) acc[o][p] = bv;
    }

    for (int icc = 0; icc < 4; ++icc) {
        __syncthreads();
        // FIX: full 16-channel tile needs 512 float4 loads = 2 per thread
        for (int idx = tid; idx < 512; idx += 256) {
            int ic = idx >> 5, q = idx & 31;
            int row = q >> 2, c4 = (q & 3) * 4;
            const float* src = xbase + (size_t)(icc*16+ic)*NPIX
                               + (size_t)(y0+row)*WW + xb + c4;
            *(float4*)&sX[ic*128 + row*16 + c4] = *(const float4*)src;
        }
        __syncthreads();

        // x-stats: sX shared by all warps -> only warp 0 contributes
        float xs0 = 0.f, xq0 = 0.f, xs1 = 0.f, xq1 = 0.f;
        bool do_stats = (half == 0) && (warp == 0);
        #pragma unroll 4
        for (int ic = 0; ic < 16; ++ic) {
            int gic = icc*16 + ic;
            float4 rv = *(float4*)&sX[ic*128 + r*16 + cb];
            if (do_stats) {
                float s = (rv.x + rv.y) + (rv.z + rv.w);
                float q = (rv.x*rv.x + rv.y*rv.y) + (rv.z*rv.z + rv.w*rv.w);
                if (ic < 8) { xs0 += s; xq0 += q; } else { xs1 += s; xq1 += q; }
            }
            #pragma unroll
            for (int o = 0; o < 4; ++o) {
                float w = sW[(warp*4 + o)*64 + gic];
                acc[o][0] = fmaf(w, rv.x, acc[o][0]);
                acc[o][1] = fmaf(w, rv.y, acc[o][1]);
                acc[o][2] = fmaf(w, rv.z, acc[o][2]);
                acc[o][3] = fmaf(w, rv.w, acc[o][3]);
            }
        }
        if (do_stats) {
            #pragma unroll
            for (int off = 16; off; off >>= 1) {
                xs0 += __shfl_xor_sync(0xffffffffu, xs0, off);
                xq0 += __shfl_xor_sync(0xffffffffu, xq0, off);
                xs1 += __shfl_xor_sync(0xffffffffu, xs1, off);
                xq1 += __shfl_xor_sync(0xffffffffu, xq1, off);
            }
            if (lane == 0) {
                atomicAdd(&g_sum_x[b*8 + icc*2],     xs0);
                atomicAdd(&g_ssq_x[b*8 + icc*2],     xq0);
                atomicAdd(&g_sum_x[b*8 + icc*2 + 1], xs1);
                atomicAdd(&g_ssq_x[b*8 + icc*2 + 1], xq1);
            }
        }
    }

    size_t pixoff = (size_t)(y0 + r) * WW + xb + cb;
    float sv = 0.f, ssv = 0.f;
    #pragma unroll
    for (int o = 0; o < 4; ++o) {
        float* sp = &g_s[cs][b][oc0 + o][0][0] + pixoff;
        *(float4*)sp = make_float4(acc[o][0], acc[o][1], acc[o][2], acc[o][3]);
        #pragma unroll
        for (int p = 0; p < 4; ++p) { sv += acc[o][p]; ssv += acc[o][p]*acc[o][p]; }
    }
    #pragma unroll
    for (int off = 16; off; off >>= 1) {
        sv  += __shfl_xor_sync(0xffffffffu, sv,  off);
        ssv += __shfl_xor_sync(0xffffffffu, ssv, off);
    }
    if (lane == 0) {
        int gi = b*8 + (oc0 >> 3);
        atomicAdd(&g_sum_s[gi], sv); atomicAdd(&g_ssq_s[gi], ssv);
    }
}

// ---------------- fused conv kernel ----------------
// grid (16, 32, 16): z = ocq*4 + cs*2 + b. 256 thr = 8 warps; warp -> 2 oc.
// smem floats: sW 16*64*8 = 8192 | scale 64 | shift 64 | same 2048 | cross 2880
#define SM_W     0
#define SM_SCALE 8192
#define SM_SHIFT 8256
#define SM_SAME  8320
#define SM_CROSS 10368
#define SM_FLOATS 13248
#define SMEM_BYTES (SM_FLOATS*4)

template<int PASS>
__global__ __launch_bounds__(256, 3)
void conv_qc_k(const float* __restrict__ in0, const float* __restrict__ in1,
               const float* __restrict__ Wc, const float* __restrict__ Wk,
               const float* __restrict__ Bi,
               const float* __restrict__ Ga, const float* __restrict__ Be,
               const float* __restrict__ Gs, const float* __restrict__ BeS,
               float* __restrict__ Out)
{
    extern __shared__ float sm[];
    float* sW     = sm + SM_W;       // [(o16*64+ic)*8]: k0..k3, center, pad
    float* sScale = sm + SM_SCALE;
    float* sShift = sm + SM_SHIFT;
    float* sSame  = sm + SM_SAME;    // [16][8][16]
    float* sCross = sm + SM_CROSS;   // [16][9][20]

    int tid = threadIdx.x, warp = tid >> 5, lane = tid & 31;
    int r = lane >> 2, cb = (lane & 3) * 4;
    int z = blockIdx.z; int b = z & 1, cs = (z >> 1) & 1, ocq = z >> 2;
    int oc0 = ocq * 16 + warp * 2;
    int y0 = blockIdx.y * 8, xb = blockIdx.x * 16;

    const float* same_base;
    const float* cross_base;
    if (PASS == 1) {
        same_base  = (cs ? in1 : in0) + (size_t)b * CC * NPIX;
        cross_base = (cs ? in0 : in1) + (size_t)b * CC * NPIX;
    } else {
        same_base  = &g_t[cs][b][0][0][0];
        cross_base = &g_t[cs ^ 1][b][0][0][0];
    }
    const float* meanA = (PASS == 1) ? g_mean1 : g_mean2;
    const float* invA  = (PASS == 1) ? g_inv1  : g_inv2;

    // this CTA's 16-oc weight slice
    for (int idx = tid; idx < 16*64; idx += 256) {
        int o = idx >> 6, ic = idx & 63;
        size_t gidx = (size_t)(ocq*16 + o) * 64 + ic;
        float4 k4 = *(const float4*)&Wk[gidx * 4];
        float* d = &sW[idx * 8];
        d[0] = k4.x; d[1] = k4.y; d[2] = k4.z; d[3] = k4.w;
        d[4] = Wc[gidx];
    }
    if (tid < CC) {
        int grp = tid >> 3;
        float m = meanA[b*8+grp], iv = invA[b*8+grp];
        float sc = iv * Ga[tid];
        sScale[tid] = sc;
        sShift[tid] = Be[tid] - m * sc;
    }

    float acc[2][4];
    #pragma unroll
    for (int o = 0; o < 2; ++o) {
        float bv = Bi[oc0 + o];
        #pragma unroll
        for (int p = 0; p < 4; ++p) acc[o][p] = bv;
    }

    for (int icc = 0; icc < 4; ++icc) {
        __syncthreads();
        // same-coset tile (raw; normalized at use)
        for (int idx = tid; idx < 512; idx += 256) {
            int ic = idx >> 5, q = idx & 31;
            int row = q >> 2, c4 = (q & 3) * 4;
            const float* src = same_base + (size_t)(icc*16+ic)*NPIX
                               + (size_t)(y0+row)*WW + xb + c4;
            *(float4*)&sSame[ic*128 + row*16 + c4] = *(const float4*)src;
        }
        // cross-coset tile with halo: 9x17 used, stride 20, normalized+relu
        for (int idx = tid; idx < 16*9*17; idx += 256) {
            int ic = idx / 153, rem = idx % 153;
            int row = rem / 17, col = rem % 17;
            int gy = y0 + cs - 1 + row;
            int gx = xb + cs - 1 + col;
            int gic = icc*16 + ic;
            float v = 0.f;
            if ((unsigned)gy < HH && (unsigned)gx < WW) {
                float raw = cross_base[(size_t)gic*NPIX + (size_t)gy*WW + gx];
                v = fmaxf(fmaf(raw, sScale[gic], sShift[gic]), 0.f);
            }
            sCross[ic*180 + row*20 + col] = v;
        }
        __syncthreads();

        #pragma unroll 4
        for (int ic = 0; ic < 16; ++ic) {
            int gic = icc*16 + ic;
            float sc = sScale[gic], sf = sShift[gic];
            float4 rv = *(float4*)&sSame[ic*128 + r*16 + cb];
            float hh[4] = { fmaxf(fmaf(rv.x, sc, sf), 0.f),
                            fmaxf(fmaf(rv.y, sc, sf), 0.f),
                            fmaxf(fmaf(rv.z, sc, sf), 0.f),
                            fmaxf(fmaf(rv.w, sc, sf), 0.f) };
            const float* crp = &sCross[ic*180 + r*20 + cb];
            float4 c0a = *(const float4*)crp;        float c04 = crp[4];
            float4 c1a = *(const float4*)(crp + 20); float c14 = crp[24];
            float c0[5] = { c0a.x, c0a.y, c0a.z, c0a.w, c04 };
            float c1[5] = { c1a.x, c1a.y, c1a.z, c1a.w, c14 };
            #pragma unroll
            for (int o = 0; o < 2; ++o) {
                const float* wb = &sW[((warp*2 + o)*64 + gic) * 8];
                float4 wk = *(const float4*)wb;
                float  wc = wb[4];
                #pragma unroll
                for (int p = 0; p < 4; ++p) {
                    float a = acc[o][p];
                    a = fmaf(wc,   hh[p],   a);
                    a = fmaf(wk.x, c0[p],   a);
                    a = fmaf(wk.y, c0[p+1], a);
                    a = fmaf(wk.z, c1[p],   a);
                    a = fmaf(wk.w, c1[p+1], a);
                    acc[o][p] = a;
                }
            }
        }
    }

    size_t pixoff = (size_t)(y0 + r) * WW + xb + cb;
    if (PASS == 1) {
        float st = 0.f, sst = 0.f;
        #pragma unroll
        for (int o = 0; o < 2; ++o) {
            float* tp = &g_t[cs][b][oc0 + o][0][0] + pixoff;
            *(float4*)tp = make_float4(acc[o][0], acc[o][1], acc[o][2], acc[o][3]);
            #pragma unroll
            for (int p = 0; p < 4; ++p) { st += acc[o][p]; sst += acc[o][p]*acc[o][p]; }
        }
        #pragma unroll
        for (int off = 16; off; off >>= 1) {
            st  += __shfl_xor_sync(0xffffffffu, st,  off);
            sst += __shfl_xor_sync(0xffffffffu, sst, off);
        }
        if (lane == 0) {
            int gi = b*8 + (oc0 >> 3);
            atomicAdd(&g_sum_t[gi], st); atomicAdd(&g_ssq_t[gi], sst);
        }
    } else {
        #pragma unroll
        for (int o = 0; o < 2; ++o) {
            int oc = oc0 + o;
            int gi = b*8 + (oc >> 3);
            float iv  = g_invs[gi];
            float gsc = Gs[oc] * iv;
            float gsh = BeS[oc] - g_means[gi] * gsc;
            const float* sp = &g_s[cs][b][oc][0][0] + pixoff;
            float4 sv4 = *(const float4*)sp;
            float4 ov;
            ov.x = acc[o][0] + fmaf(sv4.x, gsc, gsh);
            ov.y = acc[o][1] + fmaf(sv4.y, gsc, gsh);
            ov.z = acc[o][2] + fmaf(sv4.z, gsc, gsh);
            ov.w = acc[o][3] + fmaf(sv4.w, gsc, gsh);
            float* op = Out + (((size_t)cs*BB + b)*CC + oc)*NPIX + pixoff;
            *(float4*)op = ov;
        }
    }
}

// ---------------- launch ----------------
extern "C" void kernel_launch(void* const* d_in, const int* in_sizes, int n_in,
                              void* d_out, int out_size) {
    const float* x0      = (const float*)d_in[0];
    const float* x1      = (const float*)d_in[1];
    const float* g1      = (const float*)d_in[2];
    const float* b1      = (const float*)d_in[3];
    const float* w1c     = (const float*)d_in[4];
    const float* w1k     = (const float*)d_in[5];
    const float* bias1   = (const float*)d_in[6];
    const float* g2      = (const float*)d_in[7];
    const float* b2      = (const float*)d_in[8];
    const float* w2c     = (const float*)d_in[9];
    const float* w2k     = (const float*)d_in[10];
    const float* bias2   = (const float*)d_in[11];
    const float* wskip   = (const float*)d_in[12];
    const float* bskip   = (const float*)d_in[13];
    const float* gskip   = (const float*)d_in[14];
    const float* betask  = (const float*)d_in[15];

    cudaFuncSetAttribute(conv_qc_k<1>, cudaFuncAttributeMaxDynamicSharedMemorySize, SMEM_BYTES);
    cudaFuncSetAttribute(conv_qc_k<2>, cudaFuncAttributeMaxDynamicSharedMemorySize, SMEM_BYTES);

    zero_stats_k<<<1, 128>>>();
    skip_k<<<dim3(16, 32, 8), 256>>>(x0, x1, wskip, bskip);   // also x-stats
    finalize1_k<<<1, 32>>>();

    dim3 grid(WW/16, HH/8, 16);   // z = ocq*4 + cs*2 + b
    conv_qc_k<1><<<grid, 256, SMEM_BYTES>>>(x0, x1, w1c, w1k, bias1, g1, b1,
                                            nullptr, nullptr, nullptr);
    finalize2_k<<<1, 64>>>();
    conv_qc_k<2><<<grid, 256, SMEM_BYTES>>>(nullptr, nullptr, w2c, w2k, bias2, g2, b2,
                                            gskip, betask, (float*)d_out);
    (void)in_sizes; (void)n_in; (void)out_size;
}

// round 6
// speedup vs baseline: 1.8342x; 1.7137x over previous
#include <cuda_runtime.h>

#define HH 256
#define WW 256
#define BB 2
#define CC 64
#define EPSV 1e-5f
#define NPIX (HH*WW)
#define NGRP 16
#define NELEM_GRP (8*NPIX*2)

// ---------------- scratch ----------------
__device__ float g_t[2][BB][CC][HH][WW];
__device__ float g_s[2][BB][CC][HH][WW];
__device__ float g_sum_x[NGRP], g_ssq_x[NGRP];
__device__ float g_sum_t[NGRP], g_ssq_t[NGRP];
__device__ float g_sum_s[NGRP], g_ssq_s[NGRP];
__device__ float g_mean1[NGRP], g_inv1[NGRP];
__device__ float g_mean2[NGRP], g_inv2[NGRP];
__device__ float g_means[NGRP], g_invs[NGRP];

// ---------------- small kernels ----------------
__global__ void zero_stats_k() {
    int i = threadIdx.x;
    if (i < NGRP) {
        g_sum_x[i] = 0.f; g_ssq_x[i] = 0.f;
        g_sum_t[i] = 0.f; g_ssq_t[i] = 0.f;
        g_sum_s[i] = 0.f; g_ssq_s[i] = 0.f;
    }
}

__global__ void stats_x_k(const float* __restrict__ x0, const float* __restrict__ x1) {
    int slab = blockIdx.y;                     // cs*16 + b*8 + g
    int cs = slab >> 4, b = (slab >> 3) & 1, g = slab & 7;
    const float* src = (cs ? x1 : x0) + ((size_t)(b*CC + g*8)) * NPIX
                       + (size_t)blockIdx.x * 16384;
    const float4* p = (const float4*)src;
    float s = 0.f, ss = 0.f;
    for (int i = threadIdx.x; i < 4096; i += 256) {
        float4 v = p[i];
        s  += (v.x + v.y) + (v.z + v.w);
        ss += (v.x*v.x + v.y*v.y) + (v.z*v.z + v.w*v.w);
    }
    __shared__ float sh[256], sh2[256];
    sh[threadIdx.x] = s; sh2[threadIdx.x] = ss;
    __syncthreads();
    for (int o = 128; o > 0; o >>= 1) {
        if (threadIdx.x < o) { sh[threadIdx.x] += sh[threadIdx.x+o]; sh2[threadIdx.x] += sh2[threadIdx.x+o]; }
        __syncthreads();
    }
    if (threadIdx.x == 0) {
        atomicAdd(&g_sum_x[b*8+g], sh[0]);
        atomicAdd(&g_ssq_x[b*8+g], sh2[0]);
    }
}

__global__ void finalize1_k() {
    int i = threadIdx.x;
    if (i < NGRP) {
        float n = (float)NELEM_GRP;
        float m = g_sum_x[i] / n;
        float v = g_ssq_x[i] / n - m*m;
        g_mean1[i] = m; g_inv1[i] = rsqrtf(v + EPSV);
    }
}

__global__ void finalize2_k() {
    int i = threadIdx.x;
    float n = (float)NELEM_GRP;
    if (i < NGRP) {
        float m = g_sum_t[i] / n;
        float v = g_ssq_t[i] / n - m*m;
        g_mean2[i] = m; g_inv2[i] = rsqrtf(v + EPSV);
    } else if (i < 2*NGRP) {
        int j = i - NGRP;
        float m = g_sum_s[j] / n;
        float v = g_ssq_s[j] / n - m*m;
        g_means[j] = m; g_invs[j] = rsqrtf(v + EPSV);
    }
}

// ---------------- fused conv kernel (pipelined) ----------------
// 512 thr = 16 warps; warp -> 4 oc (all 64 oc per CTA); 8x16 tile; z = b + 2*cs.
#define NT 512
// smem layout (floats)
#define SM_WK    0                       // 64*64*4 = 16384
#define SM_WC    16384                   // 4096
#define SM_WS    20480                   // 4096 (pass1 only, always reserved)
#define SM_SCALE 24576                   // 64
#define SM_SHIFT 24640                   // 64
#define SM_SAME  24704                   // 2 bufs * 2048
#define SM_CROSS 28800                   // 2 bufs * 2880
#define SM_FLOATS 34560
#define SMEM_BYTES (SM_FLOATS*4)

#define CP16(dst_u32, src_ptr) \
    asm volatile("cp.async.ca.shared.global [%0], [%1], 16;" :: "r"(dst_u32), "l"(src_ptr))
#define CP_COMMIT() asm volatile("cp.async.commit_group;")
#define CP_WAIT0()  asm volatile("cp.async.wait_group 0;" ::: "memory")

template<int PASS>
__global__ __launch_bounds__(NT, 1)
void conv_qc_k(const float* __restrict__ in0, const float* __restrict__ in1,
               const float* __restrict__ Wc, const float* __restrict__ Wk,
               const float* __restrict__ Bi,
               const float* __restrict__ Ga, const float* __restrict__ Be,
               const float* __restrict__ Ws, const float* __restrict__ Bs,
               const float* __restrict__ Gs, const float* __restrict__ BeS,
               float* __restrict__ Out)
{
    extern __shared__ float sm[];
    float* sWk    = sm + SM_WK;      // [o*64+ic] float4 (taps)
    float* sWc    = sm + SM_WC;
    float* sWs    = sm + SM_WS;
    float* sScale = sm + SM_SCALE;
    float* sShift = sm + SM_SHIFT;

    int tid  = threadIdx.x;
    int warp = tid >> 5, lane = tid & 31;
    int ocb  = warp * 4;
    int r    = lane >> 2, cb = (lane & 3) * 4;
    int z = blockIdx.z; int b = z & 1, cs = z >> 1;
    int y0 = blockIdx.y * 8, xb = blockIdx.x * 16;

    const float* same_base;
    const float* cross_base;
    if (PASS == 1) {
        same_base  = (cs ? in1 : in0) + (size_t)b * CC * NPIX;
        cross_base = (cs ? in0 : in1) + (size_t)b * CC * NPIX;
    } else {
        same_base  = &g_t[cs][b][0][0][0];
        cross_base = &g_t[cs ^ 1][b][0][0][0];
    }
    const float* meanA = (PASS == 1) ? g_mean1 : g_mean2;
    const float* invA  = (PASS == 1) ? g_inv1  : g_inv2;

    // ---- weights -> smem ----
    for (int i = tid; i < 4096; i += NT) ((float4*)sWk)[i] = ((const float4*)Wk)[i];
    for (int i = tid; i < 1024; i += NT) ((float4*)sWc)[i] = ((const float4*)Wc)[i];
    if (PASS == 1)
        for (int i = tid; i < 1024; i += NT) ((float4*)sWs)[i] = ((const float4*)Ws)[i];
    if (tid < CC) {
        int grp = tid >> 3;
        float m = meanA[b*8+grp], iv = invA[b*8+grp];
        float sc = iv * Ga[tid];
        sScale[tid] = sc;
        sShift[tid] = Be[tid] - m * sc;
    }

    // ---- per-thread staging parameters (constant across icc) ----
    // same tile: one float4 per thread via cp.async
    int ic_s  = tid >> 5, q_s = tid & 31;
    int row_s = q_s >> 2, c4_s = (q_s & 3) * 4;
    const float* same_src = same_base + (size_t)ic_s*NPIX + (size_t)(y0+row_s)*WW + xb + c4_s;
    unsigned same_dst[2];
    {
        unsigned base0 = (unsigned)__cvta_generic_to_shared(sm + SM_SAME);
        unsigned off   = (unsigned)(ic_s*128 + row_s*16 + c4_s) * 4u;
        same_dst[0] = base0 + off;
        same_dst[1] = base0 + 2048*4 + off;
    }
    // cross tile: 5 elements per thread (idx = tid + k*512), 16*9*17 = 2448 total
    int  coff[5]; int cic[5]; int csm[5];
    #pragma unroll
    for (int k = 0; k < 5; ++k) {
        int idx = tid + k*NT;
        if (idx < 2448) {
            int ic = idx / 153, rem = idx % 153;
            int row = rem / 17, col = rem % 17;
            int gy = y0 + cs - 1 + row;
            int gx = xb + cs - 1 + col;
            bool inb = ((unsigned)gy < HH) && ((unsigned)gx < WW);
            coff[k] = inb ? (ic*NPIX + gy*WW + gx) : -1;
            cic[k]  = ic;
            csm[k]  = ic*180 + row*20 + col;
        } else { coff[k] = -1; cic[k] = 0; csm[k] = -1; }
    }

    __syncthreads();   // weights + scale/shift visible

    float acc[4][4], accs[4][4];
    #pragma unroll
    for (int o = 0; o < 4; ++o) {
        float bv = Bi[ocb+o];
        float bs = (PASS == 1) ? Bs[ocb+o] : 0.f;
        #pragma unroll
        for (int p = 0; p < 4; ++p) { acc[o][p] = bv; accs[o][p] = bs; }
    }

    // ---- prologue: stage chunk 0 into buffer 0 ----
    {
        CP16(same_dst[0], same_src);
        CP_COMMIT();
        float raw[5];
        #pragma unroll
        for (int k = 0; k < 5; ++k)
            raw[k] = (coff[k] >= 0) ? __ldg(cross_base + coff[k]) : 0.f;
        #pragma unroll
        for (int k = 0; k < 5; ++k) {
            if (csm[k] >= 0) {
                float v = 0.f;
                if (coff[k] >= 0) {
                    int gic = cic[k];
                    v = fmaxf(fmaf(raw[k], sScale[gic], sShift[gic]), 0.f);
                }
                sm[SM_CROSS + csm[k]] = v;
            }
        }
        CP_WAIT0();
        __syncthreads();
    }

    for (int icc = 0; icc < 4; ++icc) {
        int cur = icc & 1, nxt = cur ^ 1;
        float* sSame  = sm + SM_SAME  + cur*2048;
        float* sCross = sm + SM_CROSS + cur*2880;

        float raw[5];
        if (icc < 3) {
            CP16(same_dst[nxt], same_src + (size_t)(icc+1)*16*NPIX);
            CP_COMMIT();
            #pragma unroll
            for (int k = 0; k < 5; ++k)
                raw[k] = (coff[k] >= 0) ? __ldg(cross_base + coff[k] + (icc+1)*16*NPIX) : 0.f;
        }

        #pragma unroll 4
        for (int ic = 0; ic < 16; ++ic) {
            int gic = icc*16 + ic;
            float sc = sScale[gic], sf = sShift[gic];
            float4 rv = *(float4*)&sSame[ic*128 + r*16 + cb];
            float hh[4] = { fmaxf(fmaf(rv.x, sc, sf), 0.f),
                            fmaxf(fmaf(rv.y, sc, sf), 0.f),
                            fmaxf(fmaf(rv.z, sc, sf), 0.f),
                            fmaxf(fmaf(rv.w, sc, sf), 0.f) };
            float rw[4] = { rv.x, rv.y, rv.z, rv.w };
            const float* crp = &sCross[ic*180 + r*20 + cb];
            float4 c0a = *(const float4*)crp;        float c04 = crp[4];
            float4 c1a = *(const float4*)(crp + 20); float c14 = crp[24];
            float c0[5] = { c0a.x, c0a.y, c0a.z, c0a.w, c04 };
            float c1[5] = { c1a.x, c1a.y, c1a.z, c1a.w, c14 };
            #pragma unroll
            for (int o = 0; o < 4; ++o) {
                int oi = (ocb + o) * 64 + gic;
                float4 wk = *(float4*)&sWk[oi*4];
                float  wc = sWc[oi];
                float  wsv = (PASS == 1) ? sWs[oi] : 0.f;
                #pragma unroll
                for (int p = 0; p < 4; ++p) {
                    float a = acc[o][p];
                    a = fmaf(wc,   hh[p],   a);
                    a = fmaf(wk.x, c0[p],   a);
                    a = fmaf(wk.y, c0[p+1], a);
                    a = fmaf(wk.z, c1[p],   a);
                    a = fmaf(wk.w, c1[p+1], a);
                    acc[o][p] = a;
                    if (PASS == 1) accs[o][p] = fmaf(wsv, rw[p], accs[o][p]);
                }
            }
        }

        if (icc < 3) {
            float* dC = sm + SM_CROSS + nxt*2880;
            #pragma unroll
            for (int k = 0; k < 5; ++k) {
                if (csm[k] >= 0) {
                    float v = 0.f;
                    if (coff[k] >= 0) {
                        int gic = (icc+1)*16 + cic[k];
                        v = fmaxf(fmaf(raw[k], sScale[gic], sShift[gic]), 0.f);
                    }
                    dC[csm[k]] = v;
                }
            }
            CP_WAIT0();
        }
        __syncthreads();
    }

    size_t pixoff = (size_t)(y0 + r) * WW + xb + cb;
    if (PASS == 1) {
        float st = 0.f, sst = 0.f, sv = 0.f, ssv = 0.f;
        #pragma unroll
        for (int o = 0; o < 4; ++o) {
            int oc = ocb + o;
            float* tp = &g_t[cs][b][oc][0][0] + pixoff;
            float* sp = &g_s[cs][b][oc][0][0] + pixoff;
            *(float4*)tp = make_float4(acc[o][0], acc[o][1], acc[o][2], acc[o][3]);
            *(float4*)sp = make_float4(accs[o][0], accs[o][1], accs[o][2], accs[o][3]);
            #pragma unroll
            for (int p = 0; p < 4; ++p) {
                st += acc[o][p];  sst += acc[o][p]  * acc[o][p];
                sv += accs[o][p]; ssv += accs[o][p] * accs[o][p];
            }
        }
        #pragma unroll
        for (int off = 16; off; off >>= 1) {
            st  += __shfl_xor_sync(0xffffffffu, st,  off);
            sst += __shfl_xor_sync(0xffffffffu, sst, off);
            sv  += __shfl_xor_sync(0xffffffffu, sv,  off);
            ssv += __shfl_xor_sync(0xffffffffu, ssv, off);
        }
        if (lane == 0) {
            int gi = b*8 + (ocb >> 3);
            atomicAdd(&g_sum_t[gi], st); atomicAdd(&g_ssq_t[gi], sst);
            atomicAdd(&g_sum_s[gi], sv); atomicAdd(&g_ssq_s[gi], ssv);
        }
    } else {
        #pragma unroll
        for (int o = 0; o < 4; ++o) {
            int oc = ocb + o;
            int gi = b*8 + (oc >> 3);
            float iv  = g_invs[gi];
            float gsc = Gs[oc] * iv;
            float gsh = BeS[oc] - g_means[gi] * gsc;
            const float* sp = &g_s[cs][b][oc][0][0] + pixoff;
            float4 sv4 = *(const float4*)sp;
            float4 ov;
            ov.x = acc[o][0] + fmaf(sv4.x, gsc, gsh);
            ov.y = acc[o][1] + fmaf(sv4.y, gsc, gsh);
            ov.z = acc[o][2] + fmaf(sv4.z, gsc, gsh);
            ov.w = acc[o][3] + fmaf(sv4.w, gsc, gsh);
            float* op = Out + (((size_t)cs*BB + b)*CC + oc)*NPIX + pixoff;
            *(float4*)op = ov;
        }
    }
}

// ---------------- launch ----------------
extern "C" void kernel_launch(void* const* d_in, const int* in_sizes, int n_in,
                              void* d_out, int out_size) {
    const float* x0      = (const float*)d_in[0];
    const float* x1      = (const float*)d_in[1];
    const float* g1      = (const float*)d_in[2];
    const float* b1      = (const float*)d_in[3];
    const float* w1c     = (const float*)d_in[4];
    const float* w1k     = (const float*)d_in[5];
    const float* bias1   = (const float*)d_in[6];
    const float* g2      = (const float*)d_in[7];
    const float* b2      = (const float*)d_in[8];
    const float* w2c     = (const float*)d_in[9];
    const float* w2k     = (const float*)d_in[10];
    const float* bias2   = (const float*)d_in[11];
    const float* wskip   = (const float*)d_in[12];
    const float* bskip   = (const float*)d_in[13];
    const float* gskip   = (const float*)d_in[14];
    const float* betask  = (const float*)d_in[15];

    cudaFuncSetAttribute(conv_qc_k<1>, cudaFuncAttributeMaxDynamicSharedMemorySize, SMEM_BYTES);
    cudaFuncSetAttribute(conv_qc_k<2>, cudaFuncAttributeMaxDynamicSharedMemorySize, SMEM_BYTES);

    zero_stats_k<<<1, 128>>>();
    stats_x_k<<<dim3(32, 32), 256>>>(x0, x1);
    finalize1_k<<<1, 32>>>();

    dim3 grid(WW/16, HH/8, 4);   // z = b + 2*cs
    conv_qc_k<1><<<grid, NT, SMEM_BYTES>>>(x0, x1, w1c, w1k, bias1, g1, b1,
                                           wskip, bskip, nullptr, nullptr, nullptr);
    finalize2_k<<<1, 64>>>();
    conv_qc_k<2><<<grid, NT, SMEM_BYTES>>>(nullptr, nullptr, w2c, w2k, bias2, g2, b2,
                                           nullptr, nullptr, gskip, betask, (float*)d_out);
    (void)in_sizes; (void)n_in; (void)out_size;
}